// round 1
// baseline (speedup 1.0000x reference)
#include <cuda_runtime.h>
#include <cstdint>

// BidirectionalSoftmax: B=8, L1=L2=2048, fp32.
// out[b,i,j] = mask ? sqrt(EPS + row_softmax * col_softmax) : 0
// With TAU=0.5 and N(0,1) data, exp(s/TAU) stays well inside fp32 range,
// so no max-subtraction is needed:
//   rowsum[b,i] = sum_{j<len2} exp(2*s),  colsum[b,j] = sum_{i<len1} exp(2*s)
//   out = sqrt(EPS + exp(4*s) * inv_rowsum * inv_colsum)

constexpr int B_  = 8;
constexpr int L1_ = 2048;
constexpr int L2_ = 2048;
constexpr float INV_TAU = 2.0f;   // 1/0.5
constexpr float EPS_ = 1e-8f;

// Scratch (no allocations allowed — device globals)
__device__ float g_inv_rowsum[B_ * L1_];
__device__ float g_colsum[B_ * L2_];

// ---------------------------------------------------------------------------
__global__ void zero_colsum_kernel() {
    int t = blockIdx.x * blockDim.x + threadIdx.x;
    if (t < B_ * L2_) g_colsum[t] = 0.0f;
}

// ---------------------------------------------------------------------------
// Fused row+col stats in ONE read of sim.
// grid (L1/32, B), block 512 = 16 warps.
// Warp w owns column stripe [w*128, (w+1)*128). Lane owns 4 consecutive cols
// (float4). Block covers 32 rows. Column partials live in registers; row sums
// go through a shuffle reduce + padded shared array (conflict-free).
__global__ __launch_bounds__(512) void stats_kernel(
    const float* __restrict__ sim, const int* __restrict__ lengths)
{
    const int b    = blockIdx.y;
    const int i0   = blockIdx.x * 32;
    const int len1 = lengths[2 * b + 0];
    const int len2 = lengths[2 * b + 1];
    const int warp = threadIdx.x >> 5;
    const int lane = threadIdx.x & 31;
    const int j    = warp * 128 + lane * 4;

    // stride-33 padding -> conflict-free in the final reduce
    __shared__ float rs_part[16 * 33];

    const bool m0 = (j + 0) < len2;
    const bool m1 = (j + 1) < len2;
    const bool m2 = (j + 2) < len2;
    const bool m3 = (j + 3) < len2;

    float c0 = 0.f, c1 = 0.f, c2 = 0.f, c3 = 0.f;

    const float* base = sim + ((size_t)b * L1_ + i0) * L2_ + j;

    #pragma unroll 4
    for (int r = 0; r < 32; r++) {
        float4 v = *(const float4*)(base + (size_t)r * L2_);
        float e0 = m0 ? __expf(v.x * INV_TAU) : 0.f;
        float e1 = m1 ? __expf(v.y * INV_TAU) : 0.f;
        float e2 = m2 ? __expf(v.z * INV_TAU) : 0.f;
        float e3 = m3 ? __expf(v.w * INV_TAU) : 0.f;

        float rsum = (e0 + e1) + (e2 + e3);
        #pragma unroll
        for (int off = 16; off > 0; off >>= 1)
            rsum += __shfl_down_sync(0xffffffffu, rsum, off);
        if (lane == 0) rs_part[warp * 33 + r] = rsum;

        if ((i0 + r) < len1) { c0 += e0; c1 += e1; c2 += e2; c3 += e3; }
    }
    __syncthreads();

    // Rows: thread t<32 sums the 16 warp partials for its row.
    if (threadIdx.x < 32) {
        float s = 0.f;
        #pragma unroll
        for (int w = 0; w < 16; w++) s += rs_part[w * 33 + threadIdx.x];
        g_inv_rowsum[b * L1_ + i0 + threadIdx.x] = (s > 0.f) ? __frcp_rn(s) : 0.f;
    }

    // Columns: 4 atomics per thread (2048/block, ~1M total — negligible)
    float* cb = g_colsum + b * L2_ + j;
    atomicAdd(cb + 0, c0);
    atomicAdd(cb + 1, c1);
    atomicAdd(cb + 2, c2);
    atomicAdd(cb + 3, c3);
}

// ---------------------------------------------------------------------------
__global__ void invert_colsum_kernel() {
    int t = blockIdx.x * blockDim.x + threadIdx.x;
    if (t < B_ * L2_) {
        float v = g_colsum[t];
        g_colsum[t] = (v > 0.f) ? __frcp_rn(v) : 0.f;
    }
}

// ---------------------------------------------------------------------------
// One block per output row. float4 loads/stores; zeros everywhere masked
// (d_out is poisoned, so every element must be written).
__global__ __launch_bounds__(256) void out_kernel(
    const float* __restrict__ sim, const int* __restrict__ lengths,
    float* __restrict__ out)
{
    const int b = blockIdx.y;
    const int i = blockIdx.x;
    const int len1 = lengths[2 * b + 0];
    const int len2 = lengths[2 * b + 1];

    const size_t rowoff = ((size_t)b * L1_ + i) * L2_;
    float4* o = (float4*)(out + rowoff);

    if (i >= len1) {
        const float4 z = make_float4(0.f, 0.f, 0.f, 0.f);
        o[threadIdx.x]       = z;
        o[threadIdx.x + 256] = z;
        return;
    }

    const float inv_rs = g_inv_rowsum[b * L1_ + i];
    const float4* s  = (const float4*)(sim + rowoff);
    const float4* ic = (const float4*)(g_colsum + b * L2_);

    #pragma unroll
    for (int it = 0; it < 2; it++) {
        const int idx = threadIdx.x + it * 256;
        const int j   = idx * 4;
        float4 v = s[idx];
        float4 c = ic[idx];
        float4 r;
        {
            float p = __expf(v.x * (2.f * INV_TAU)) * inv_rs * c.x + EPS_;
            r.x = ((j + 0) < len2) ? __fsqrt_rn(p) : 0.f;
        }
        {
            float p = __expf(v.y * (2.f * INV_TAU)) * inv_rs * c.y + EPS_;
            r.y = ((j + 1) < len2) ? __fsqrt_rn(p) : 0.f;
        }
        {
            float p = __expf(v.z * (2.f * INV_TAU)) * inv_rs * c.z + EPS_;
            r.z = ((j + 2) < len2) ? __fsqrt_rn(p) : 0.f;
        }
        {
            float p = __expf(v.w * (2.f * INV_TAU)) * inv_rs * c.w + EPS_;
            r.w = ((j + 3) < len2) ? __fsqrt_rn(p) : 0.f;
        }
        o[idx] = r;
    }
}

// ---------------------------------------------------------------------------
extern "C" void kernel_launch(void* const* d_in, const int* in_sizes, int n_in,
                              void* d_out, int out_size)
{
    const float* sim     = (const float*)d_in[0];
    const int*   lengths = (const int*)d_in[1];
    float*       out     = (float*)d_out;

    zero_colsum_kernel<<<(B_ * L2_ + 255) / 256, 256>>>();
    stats_kernel<<<dim3(L1_ / 32, B_), 512>>>(sim, lengths);
    invert_colsum_kernel<<<(B_ * L2_ + 255) / 256, 256>>>();
    out_kernel<<<dim3(L1_, B_), 256>>>(sim, lengths, out);
}